// round 4
// baseline (speedup 1.0000x reference)
#include <cuda_runtime.h>
#include <cstdint>

#define B_TOTAL 262144
#define HALF_B  131072
#define D_DIM   64
#define NR      32
#define NC      32
#define SN      32
#define ZN      32

// shared memory layout in floats
#define SM_WPZ   0          // 1024  W_pz[32][32]
#define SM_WR    1024       // 4096  W_real[32][64][2]
#define SM_WC    5120       // 8192  W_cat[32][64][4]
#define SM_BPZ   13312      // 32
#define SM_BR    13344      // 64
#define SM_BC    13408      // 128
#define SM_TOTAL 13536      // floats -> 54144 bytes

// ---------------- threefry2x32 (JAX schedule) ----------------
#define TF_ROUND(r) do { x0 += x1; x1 = (x1 << (r)) | (x1 >> (32 - (r))); x1 ^= x0; } while (0)

__host__ __device__ __forceinline__ void threefry_full(unsigned k0, unsigned k1,
                                                       unsigned x0, unsigned x1,
                                                       unsigned &o0, unsigned &o1) {
    const unsigned k2 = k0 ^ k1 ^ 0x1BD11BDAu;
    x0 += k0; x1 += k1;
    TF_ROUND(13); TF_ROUND(15); TF_ROUND(26); TF_ROUND(6);
    x0 += k1; x1 += k2 + 1u;
    TF_ROUND(17); TF_ROUND(29); TF_ROUND(16); TF_ROUND(24);
    x0 += k2; x1 += k0 + 2u;
    TF_ROUND(13); TF_ROUND(15); TF_ROUND(26); TF_ROUND(6);
    x0 += k0; x1 += k1 + 3u;
    TF_ROUND(17); TF_ROUND(29); TF_ROUND(16); TF_ROUND(24);
    x0 += k1; x1 += k2 + 4u;
    TF_ROUND(13); TF_ROUND(15); TF_ROUND(26); TF_ROUND(6);
    x0 += k2; x1 += k0 + 5u;
    o0 = x0; o1 = x1;
}

// Partitionable threefry 32-bit sample: counter pair (hi=0, lo=ctr), folded o0^o1.
// (jax_threefry_partitionable=True semantics: _threefry_random_bits_partitionable)
__device__ __forceinline__ unsigned tf_fold(unsigned k0, unsigned k1, unsigned k2,
                                            unsigned ctr) {
    unsigned x0 = k0;            // 0 + k0
    unsigned x1 = ctr + k1;
    TF_ROUND(13); TF_ROUND(15); TF_ROUND(26); TF_ROUND(6);
    x0 += k1; x1 += k2 + 1u;
    TF_ROUND(17); TF_ROUND(29); TF_ROUND(16); TF_ROUND(24);
    x0 += k2; x1 += k0 + 2u;
    TF_ROUND(13); TF_ROUND(15); TF_ROUND(26); TF_ROUND(6);
    x0 += k0; x1 += k1 + 3u;
    TF_ROUND(17); TF_ROUND(29); TF_ROUND(16); TF_ROUND(24);
    x0 += k1; x1 += k2 + 4u;
    TF_ROUND(13); TF_ROUND(15); TF_ROUND(26); TF_ROUND(6);
    x0 += k2; x1 += k0 + 5u;
    return x0 ^ x1;
}

// bits -> float in [0, 1-2^-23]  (JAX uniform mantissa trick)
__device__ __forceinline__ float bits_to_unit(unsigned b) {
    return __uint_as_float((b >> 9) | 0x3f800000u) - 1.0f;
}

// XLA ErfInv32 (Giles polynomial) — matches lax.erf_inv on f32
__device__ __forceinline__ float erfinv_xla(float x) {
    float w = -log1pf(-x * x);
    float p;
    if (w < 5.0f) {
        w = w - 2.5f;
        p = 2.81022636e-08f;
        p = fmaf(p, w, 3.43273939e-07f);
        p = fmaf(p, w, -3.5233877e-06f);
        p = fmaf(p, w, -4.39150654e-06f);
        p = fmaf(p, w, 0.00021858087f);
        p = fmaf(p, w, -0.00125372503f);
        p = fmaf(p, w, -0.00417768164f);
        p = fmaf(p, w, 0.246640727f);
        p = fmaf(p, w, 1.50140941f);
    } else {
        w = sqrtf(w) - 3.0f;
        p = -0.000200214257f;
        p = fmaf(p, w, 0.000100950558f);
        p = fmaf(p, w, 0.00134934322f);
        p = fmaf(p, w, -0.00367342844f);
        p = fmaf(p, w, 0.00573950773f);
        p = fmaf(p, w, -0.0076224613f);
        p = fmaf(p, w, 0.00943887047f);
        p = fmaf(p, w, 1.00167406f);
        p = fmaf(p, w, 2.83297682f);
    }
    return p * x;
}

// JAX normal: u = uniform(lo=nextafter(-1,0), hi=1); sqrt(2)*erfinv(u)
__device__ __forceinline__ float normal_from_bits(unsigned b) {
    float f = bits_to_unit(b);
    float u = fmaf(f, 2.0f, -0.99999994f);   // (hi-lo) rounds to 2.0f in f32
    u = fmaxf(-0.99999994f, u);
    return 1.41421356f * erfinv_xla(u);
}

// JAX gumbel: -log(-log(uniform(tiny, 1)))
// inner log via log1pf for u near 1 (robust under fast-math)
__device__ __forceinline__ float gumbel_from_bits(unsigned b) {
    float f = bits_to_unit(b);
    float t;
    if (f > 0.5f) t = -log1pf(f - 1.0f);
    else          t = -logf(fmaxf(f, 1.17549435e-38f));
    return -logf(t);
}

// categorical post-processing for one row: softmax logp + gumbel argmax
__device__ __forceinline__ void cat_row(float l1, float l2, float l3, float l4,
                                        const unsigned gb[5],
                                        const float* __restrict__ data5, float miss,
                                        float &out_val, float &lp_val) {
    float m = fmaxf(0.0f, fmaxf(fmaxf(l1, l2), fmaxf(l3, l4)));
    float e0 = expf(0.0f - m);
    float e1 = expf(l1 - m);
    float e2 = expf(l2 - m);
    float e3 = expf(l3 - m);
    float e4 = expf(l4 - m);
    float S  = ((e0 + e1) + (e2 + e3)) + e4;
    float logS = logf(S);
    // log(softmax_k + 1e-20) == (l_k - m) - logS  (p_k >> 1e-14 always here)
    float lp =            data5[0] * ((0.0f - m) - logS);
    lp = fmaf(data5[1], (l1 - m) - logS, lp);
    lp = fmaf(data5[2], (l2 - m) - logS, lp);
    lp = fmaf(data5[3], (l3 - m) - logS, lp);
    lp = fmaf(data5[4], (l4 - m) - logS, lp);
    lp_val = lp * miss;

    float z0 = gumbel_from_bits(gb[0]);              // l0 = 0
    float z1 = l1 + gumbel_from_bits(gb[1]);
    float z2 = l2 + gumbel_from_bits(gb[2]);
    float z3 = l3 + gumbel_from_bits(gb[3]);
    float z4 = l4 + gumbel_from_bits(gb[4]);
    float best = z0; int arg = 0;
    if (z1 > best) { best = z1; arg = 1; }
    if (z2 > best) { best = z2; arg = 2; }
    if (z3 > best) { best = z3; arg = 3; }
    if (z4 > best) { best = z4; arg = 4; }
    out_val = (float)arg;
}

__global__ __launch_bounds__(256)
void decoder_kernel(const float* __restrict__ y_lat, const float* __restrict__ samp_s,
                    const float* __restrict__ onehot, const int* __restrict__ miss_mask,
                    const float* __restrict__ W_pz, const float* __restrict__ b_pz,
                    const float* __restrict__ W_real, const float* __restrict__ b_real,
                    const float* __restrict__ W_cat, const float* __restrict__ b_cat,
                    float* __restrict__ out,
                    unsigned kn0, unsigned kn1, unsigned kn2,
                    unsigned kg0, unsigned kg1, unsigned kg2) {
    extern __shared__ float sm[];
    {
        const int tid = threadIdx.x;
        const int nt = blockDim.x;
#define CPY4(dst, src, nfl) \
        for (int i = tid; i < (nfl) / 4; i += nt) \
            ((float4*)(sm + (dst)))[i] = ((const float4*)(src))[i];
        CPY4(SM_WPZ, W_pz,   1024)
        CPY4(SM_WR,  W_real, 4096)
        CPY4(SM_WC,  W_cat,  8192)
        CPY4(SM_BPZ, b_pz,   32)
        CPY4(SM_BR,  b_real, 64)
        CPY4(SM_BC,  b_cat,  128)
#undef CPY4
    }
    __syncthreads();

    const int t = blockIdx.x * blockDim.x + threadIdx.x;   // 0 .. HALF_B-1
    const int bA = t;
    const int bB = t + HALF_B;

    float* o_out = out;
    float* o_mpz = out + (size_t)B_TOTAL * 64;
    float* o_lvz = out + (size_t)B_TOTAL * 96;
    float* o_lpx = out + (size_t)B_TOTAL * 128;

    // ================= pz: mean_pz = s @ W_pz^T + b_pz; logvar = 0 =================
    {
        float sA[SN], sB[SN];
        const float4* pA = (const float4*)(samp_s + (size_t)bA * SN);
        const float4* pB = (const float4*)(samp_s + (size_t)bB * SN);
#pragma unroll
        for (int i = 0; i < 8; i++) {
            float4 v = pA[i]; sA[4*i] = v.x; sA[4*i+1] = v.y; sA[4*i+2] = v.z; sA[4*i+3] = v.w;
            float4 w = pB[i]; sB[4*i] = w.x; sB[4*i+1] = w.y; sB[4*i+2] = w.z; sB[4*i+3] = w.w;
        }
        const float4 zero4 = make_float4(0.f, 0.f, 0.f, 0.f);
#pragma unroll
        for (int z4 = 0; z4 < ZN; z4 += 4) {
            float mA[4], mB[4];
#pragma unroll
            for (int zz = 0; zz < 4; zz++) {
                const int z = z4 + zz;
                float a0 = 0.f, a1 = 0.f, a2 = 0.f, a3 = 0.f;
                float c0 = 0.f, c1 = 0.f, c2 = 0.f, c3 = 0.f;
                const float4* wrow = (const float4*)(sm + SM_WPZ + z * SN);
#pragma unroll
                for (int j = 0; j < 8; j++) {
                    float4 w = wrow[j];
                    a0 = fmaf(w.x, sA[4*j],   a0);
                    a1 = fmaf(w.y, sA[4*j+1], a1);
                    a2 = fmaf(w.z, sA[4*j+2], a2);
                    a3 = fmaf(w.w, sA[4*j+3], a3);
                    c0 = fmaf(w.x, sB[4*j],   c0);
                    c1 = fmaf(w.y, sB[4*j+1], c1);
                    c2 = fmaf(w.z, sB[4*j+2], c2);
                    c3 = fmaf(w.w, sB[4*j+3], c3);
                }
                const float bias = sm[SM_BPZ + z];
                mA[zz] = bias + ((a0 + a1) + (a2 + a3));
                mB[zz] = bias + ((c0 + c1) + (c2 + c3));
            }
            *(float4*)(o_mpz + (size_t)bA * ZN + z4) = make_float4(mA[0], mA[1], mA[2], mA[3]);
            *(float4*)(o_mpz + (size_t)bB * ZN + z4) = make_float4(mB[0], mB[1], mB[2], mB[3]);
            *(float4*)(o_lvz + (size_t)bA * ZN + z4) = zero4;
            *(float4*)(o_lvz + (size_t)bB * ZN + z4) = zero4;
        }
    }

    // ================= load y for both rows (register resident) =================
    float yA[D_DIM], yB[D_DIM];
    {
        const float4* pA = (const float4*)(y_lat + (size_t)bA * D_DIM);
        const float4* pB = (const float4*)(y_lat + (size_t)bB * D_DIM);
#pragma unroll
        for (int i = 0; i < 16; i++) {
            float4 v = pA[i]; yA[4*i] = v.x; yA[4*i+1] = v.y; yA[4*i+2] = v.z; yA[4*i+3] = v.w;
            float4 w = pB[i]; yB[4*i] = w.x; yB[4*i+1] = w.y; yB[4*i+2] = w.z; yB[4*i+3] = w.w;
        }
    }

    // ================= real features =================
#pragma unroll 1
    for (int r4 = 0; r4 < NR; r4 += 4) {
        float4 dA4 = *(const float4*)(onehot + (size_t)bA * 192 + r4);
        float4 dB4 = *(const float4*)(onehot + (size_t)bB * 192 + r4);
        int4  msA4 = *(const int4*)(miss_mask + (size_t)bA * 64 + r4);
        int4  msB4 = *(const int4*)(miss_mask + (size_t)bB * 64 + r4);
        float dAarr[4] = {dA4.x, dA4.y, dA4.z, dA4.w};
        float dBarr[4] = {dB4.x, dB4.y, dB4.z, dB4.w};
        int   mAarr[4] = {msA4.x, msA4.y, msA4.z, msA4.w};
        int   mBarr[4] = {msB4.x, msB4.y, msB4.z, msB4.w};
        float outA[4], outB[4], lpA[4], lpB[4];
#pragma unroll
        for (int rr = 0; rr < 4; rr++) {
            const int r = r4 + rr;
            float mA = sm[SM_BR + 2*r], vA = sm[SM_BR + 2*r + 1];
            float mB = mA, vB = vA;
            const float4* w4 = (const float4*)(sm + SM_WR + r * 128);
#pragma unroll
            for (int d2 = 0; d2 < 32; d2++) {
                float4 w = w4[d2];
                const int d = 2 * d2;
                mA = fmaf(yA[d],   w.x, mA);
                vA = fmaf(yA[d],   w.y, vA);
                mA = fmaf(yA[d+1], w.z, mA);
                vA = fmaf(yA[d+1], w.w, vA);
                mB = fmaf(yB[d],   w.x, mB);
                vB = fmaf(yB[d],   w.y, vB);
                mB = fmaf(yB[d+1], w.z, mB);
                vB = fmaf(yB[d+1], w.w, vB);
            }
            // partitionable stream: one fold per element, counter = flat index
            const float nA = normal_from_bits(tf_fold(kn0, kn1, kn2,
                                              (unsigned)bA * 32u + (unsigned)r));
            const float nB = normal_from_bits(tf_fold(kn0, kn1, kn2,
                                              (unsigned)bB * 32u + (unsigned)r));

            float dA = dAarr[rr]; if (dA != dA) dA = 0.f;   // nan_to_num
            float dB = dBarr[rr]; if (dB != dB) dB = 0.f;
            const float missA = (float)mAarr[rr];
            const float missB = (float)mBarr[rr];
            const float diffA = dA - mA;
            const float diffB = dB - mB;
            lpA[rr] = -0.5f * ((1.8378770664f + vA) + diffA * diffA * expf(-vA)) * missA;
            lpB[rr] = -0.5f * ((1.8378770664f + vB) + diffB * diffB * expf(-vB)) * missB;
            outA[rr] = fmaf(expf(0.5f * vA), nA, mA);
            outB[rr] = fmaf(expf(0.5f * vB), nB, mB);
        }
        *(float4*)(o_out + (size_t)bA * 64 + r4) = make_float4(outA[0], outA[1], outA[2], outA[3]);
        *(float4*)(o_out + (size_t)bB * 64 + r4) = make_float4(outB[0], outB[1], outB[2], outB[3]);
        *(float4*)(o_lpx + (size_t)bA * 64 + r4) = make_float4(lpA[0], lpA[1], lpA[2], lpA[3]);
        *(float4*)(o_lpx + (size_t)bB * 64 + r4) = make_float4(lpB[0], lpB[1], lpB[2], lpB[3]);
    }

    // ================= categorical features =================
#pragma unroll 1
    for (int c = 0; c < NC; c++) {
        float4 bc = *(const float4*)(sm + SM_BC + 4 * c);
        float l1A = bc.x, l2A = bc.y, l3A = bc.z, l4A = bc.w;
        float l1B = bc.x, l2B = bc.y, l3B = bc.z, l4B = bc.w;
        const float4* w4 = (const float4*)(sm + SM_WC + c * 256);
#pragma unroll
        for (int d = 0; d < 64; d++) {
            float4 w = w4[d];
            const float ya = yA[d], yb = yB[d];
            l1A = fmaf(ya, w.x, l1A);
            l2A = fmaf(ya, w.y, l2A);
            l3A = fmaf(ya, w.z, l3A);
            l4A = fmaf(ya, w.w, l4A);
            l1B = fmaf(yb, w.x, l1B);
            l2B = fmaf(yb, w.y, l2B);
            l3B = fmaf(yb, w.z, l3B);
            l4B = fmaf(yb, w.w, l4B);
        }
        const unsigned baseA = ((unsigned)bA * 32u + (unsigned)c) * 5u;
        const unsigned baseB = ((unsigned)bB * 32u + (unsigned)c) * 5u;
        unsigned gA[5], gB[5];
#pragma unroll
        for (int k = 0; k < 5; k++) {
            gA[k] = tf_fold(kg0, kg1, kg2, baseA + (unsigned)k);
            gB[k] = tf_fold(kg0, kg1, kg2, baseB + (unsigned)k);
        }
        float dat5A[5], dat5B[5];
        const float* pdA = onehot + (size_t)bA * 192 + 32 + 5 * c;
        const float* pdB = onehot + (size_t)bB * 192 + 32 + 5 * c;
#pragma unroll
        for (int k = 0; k < 5; k++) { dat5A[k] = pdA[k]; dat5B[k] = pdB[k]; }
        const float missA = (float)miss_mask[(size_t)bA * 64 + 32 + c];
        const float missB = (float)miss_mask[(size_t)bB * 64 + 32 + c];

        float ovA, lvA, ovB, lvB;
        cat_row(l1A, l2A, l3A, l4A, gA, dat5A, missA, ovA, lvA);
        cat_row(l1B, l2B, l3B, l4B, gB, dat5B, missB, ovB, lvB);

        o_out[(size_t)bA * 64 + 32 + c] = ovA;
        o_out[(size_t)bB * 64 + 32 + c] = ovB;
        o_lpx[(size_t)bA * 64 + 32 + c] = lvA;
        o_lpx[(size_t)bB * 64 + 32 + c] = lvB;
    }
}

extern "C" void kernel_launch(void* const* d_in, const int* in_sizes, int n_in,
                              void* d_out, int out_size) {
    const float* y_lat  = (const float*)d_in[0];
    const float* samp_s = (const float*)d_in[1];
    const float* onehot = (const float*)d_in[2];
    // d_in[3] = static_types (compile-time known layout; unused)
    const int*   mask   = (const int*)d_in[4];
    const float* W_pz   = (const float*)d_in[5];
    const float* b_pz   = (const float*)d_in[6];
    const float* W_real = (const float*)d_in[7];
    const float* b_real = (const float*)d_in[8];
    const float* W_cat  = (const float*)d_in[9];
    const float* b_cat  = (const float*)d_in[10];
    float* out = (float*)d_out;

    // jax.random.key(42) = (0, 42); split -> k_norm, k_gum
    // Partitionable (foldlike) split: key_i = threefry((0,42), (0, i)), both words.
    unsigned kn0, kn1, kg0, kg1;
    threefry_full(0u, 42u, 0u, 0u, kn0, kn1);   // k_norm
    threefry_full(0u, 42u, 0u, 1u, kg0, kg1);   // k_gum
    const unsigned kn2 = kn0 ^ kn1 ^ 0x1BD11BDAu;
    const unsigned kg2 = kg0 ^ kg1 ^ 0x1BD11BDAu;

    cudaFuncSetAttribute(decoder_kernel,
                         cudaFuncAttributeMaxDynamicSharedMemorySize, SM_TOTAL * 4);
    decoder_kernel<<<HALF_B / 256, 256, SM_TOTAL * 4>>>(
        y_lat, samp_s, onehot, mask, W_pz, b_pz, W_real, b_real, W_cat, b_cat,
        out, kn0, kn1, kn2, kg0, kg1, kg2);
}

// round 5
// speedup vs baseline: 1.7448x; 1.7448x over previous
#include <cuda_runtime.h>
#include <cstdint>

#define B_TOTAL 262144
#define D_DIM   64
#define NR      32
#define NC      32
#define SN      32
#define ZN      32

// shared memory layout in floats
#define SM_WPZ   0          // 1024  W_pz[32][32]
#define SM_WR    1024       // 4096  W_real[32][64][2]
#define SM_WC    5120       // 8192  W_cat[32][64][4]
#define SM_BPZ   13312      // 32
#define SM_BR    13344      // 64
#define SM_BC    13408      // 128
#define SM_TOTAL 13536      // floats -> 54144 bytes

// ---------------- threefry2x32 (JAX schedule) ----------------
#define TF_ROUND(r) do { x0 += x1; x1 = (x1 << (r)) | (x1 >> (32 - (r))); x1 ^= x0; } while (0)

__host__ __device__ __forceinline__ void threefry_full(unsigned k0, unsigned k1,
                                                       unsigned x0, unsigned x1,
                                                       unsigned &o0, unsigned &o1) {
    const unsigned k2 = k0 ^ k1 ^ 0x1BD11BDAu;
    x0 += k0; x1 += k1;
    TF_ROUND(13); TF_ROUND(15); TF_ROUND(26); TF_ROUND(6);
    x0 += k1; x1 += k2 + 1u;
    TF_ROUND(17); TF_ROUND(29); TF_ROUND(16); TF_ROUND(24);
    x0 += k2; x1 += k0 + 2u;
    TF_ROUND(13); TF_ROUND(15); TF_ROUND(26); TF_ROUND(6);
    x0 += k0; x1 += k1 + 3u;
    TF_ROUND(17); TF_ROUND(29); TF_ROUND(16); TF_ROUND(24);
    x0 += k1; x1 += k2 + 4u;
    TF_ROUND(13); TF_ROUND(15); TF_ROUND(26); TF_ROUND(6);
    x0 += k2; x1 += k0 + 5u;
    o0 = x0; o1 = x1;
}

// Partitionable threefry 32-bit sample: counter pair (hi=0, lo=ctr), folded o0^o1.
__device__ __forceinline__ unsigned tf_fold(unsigned k0, unsigned k1, unsigned k2,
                                            unsigned ctr) {
    unsigned x0 = k0;            // 0 + k0
    unsigned x1 = ctr + k1;
    TF_ROUND(13); TF_ROUND(15); TF_ROUND(26); TF_ROUND(6);
    x0 += k1; x1 += k2 + 1u;
    TF_ROUND(17); TF_ROUND(29); TF_ROUND(16); TF_ROUND(24);
    x0 += k2; x1 += k0 + 2u;
    TF_ROUND(13); TF_ROUND(15); TF_ROUND(26); TF_ROUND(6);
    x0 += k0; x1 += k1 + 3u;
    TF_ROUND(17); TF_ROUND(29); TF_ROUND(16); TF_ROUND(24);
    x0 += k1; x1 += k2 + 4u;
    TF_ROUND(13); TF_ROUND(15); TF_ROUND(26); TF_ROUND(6);
    x0 += k2; x1 += k0 + 5u;
    return x0 ^ x1;
}

// bits -> float in [0, 1-2^-23]  (JAX uniform mantissa trick)
__device__ __forceinline__ float bits_to_unit(unsigned b) {
    return __uint_as_float((b >> 9) | 0x3f800000u) - 1.0f;
}

// XLA ErfInv32 (Giles polynomial) — matches lax.erf_inv on f32 (fast-log variant)
__device__ __forceinline__ float erfinv_xla(float x) {
    float w = -__logf(fmaf(-x, x, 1.0f));
    float p;
    if (w < 5.0f) {
        w = w - 2.5f;
        p = 2.81022636e-08f;
        p = fmaf(p, w, 3.43273939e-07f);
        p = fmaf(p, w, -3.5233877e-06f);
        p = fmaf(p, w, -4.39150654e-06f);
        p = fmaf(p, w, 0.00021858087f);
        p = fmaf(p, w, -0.00125372503f);
        p = fmaf(p, w, -0.00417768164f);
        p = fmaf(p, w, 0.246640727f);
        p = fmaf(p, w, 1.50140941f);
    } else {
        w = sqrtf(w) - 3.0f;
        p = -0.000200214257f;
        p = fmaf(p, w, 0.000100950558f);
        p = fmaf(p, w, 0.00134934322f);
        p = fmaf(p, w, -0.00367342844f);
        p = fmaf(p, w, 0.00573950773f);
        p = fmaf(p, w, -0.0076224613f);
        p = fmaf(p, w, 0.00943887047f);
        p = fmaf(p, w, 1.00167406f);
        p = fmaf(p, w, 2.83297682f);
    }
    return p * x;
}

// JAX normal: u = uniform(lo=nextafter(-1,0), hi=1); sqrt(2)*erfinv(u)
__device__ __forceinline__ float normal_from_bits(unsigned b) {
    float f = bits_to_unit(b);
    float u = fmaf(f, 2.0f, -0.99999994f);   // (hi-lo) rounds to 2.0f in f32
    u = fmaxf(-0.99999994f, u);
    return 1.41421356f * erfinv_xla(u);
}

// JAX gumbel: -log(-log(uniform(tiny, 1)))
// Feeds ONLY the argmax; MUFU-log abs error near u->1 cannot flip the winner
// (that class wins by ~+15 either way).
__device__ __forceinline__ float gumbel_from_bits(unsigned b) {
    float f = bits_to_unit(b);
    float t = -__logf(fmaxf(f, 1.17549435e-38f));
    t = fmaxf(t, 1.17549435e-38f);
    return -__logf(t);
}

// categorical post-processing for one row: softmax logp + gumbel argmax
__device__ __forceinline__ void cat_row(float l1, float l2, float l3, float l4,
                                        const unsigned gb[5],
                                        const float* __restrict__ data5, float miss,
                                        float &out_val, float &lp_val) {
    float m = fmaxf(0.0f, fmaxf(fmaxf(l1, l2), fmaxf(l3, l4)));
    float e0 = __expf(0.0f - m);
    float e1 = __expf(l1 - m);
    float e2 = __expf(l2 - m);
    float e3 = __expf(l3 - m);
    float e4 = __expf(l4 - m);
    float S  = ((e0 + e1) + (e2 + e3)) + e4;
    float logS = __logf(S);
    // log(softmax_k + 1e-20) == (l_k - m) - logS  (p_k >> 1e-14 always here)
    float lp =            data5[0] * ((0.0f - m) - logS);
    lp = fmaf(data5[1], (l1 - m) - logS, lp);
    lp = fmaf(data5[2], (l2 - m) - logS, lp);
    lp = fmaf(data5[3], (l3 - m) - logS, lp);
    lp = fmaf(data5[4], (l4 - m) - logS, lp);
    lp_val = lp * miss;

    float z0 = gumbel_from_bits(gb[0]);              // l0 = 0
    float z1 = l1 + gumbel_from_bits(gb[1]);
    float z2 = l2 + gumbel_from_bits(gb[2]);
    float z3 = l3 + gumbel_from_bits(gb[3]);
    float z4 = l4 + gumbel_from_bits(gb[4]);
    float best = z0; int arg = 0;
    if (z1 > best) { best = z1; arg = 1; }
    if (z2 > best) { best = z2; arg = 2; }
    if (z3 > best) { best = z3; arg = 3; }
    if (z4 > best) { best = z4; arg = 4; }
    out_val = (float)arg;
}

__global__ __launch_bounds__(256, 2)
void decoder_kernel(const float* __restrict__ y_lat, const float* __restrict__ samp_s,
                    const float* __restrict__ onehot, const int* __restrict__ miss_mask,
                    const float* __restrict__ W_pz, const float* __restrict__ b_pz,
                    const float* __restrict__ W_real, const float* __restrict__ b_real,
                    const float* __restrict__ W_cat, const float* __restrict__ b_cat,
                    float* __restrict__ out,
                    unsigned kn0, unsigned kn1, unsigned kn2,
                    unsigned kg0, unsigned kg1, unsigned kg2) {
    extern __shared__ float sm[];
    {
        const int tid = threadIdx.x;
        const int nt = blockDim.x;
#define CPY4(dst, src, nfl) \
        for (int i = tid; i < (nfl) / 4; i += nt) \
            ((float4*)(sm + (dst)))[i] = ((const float4*)(src))[i];
        CPY4(SM_WPZ, W_pz,   1024)
        CPY4(SM_WR,  W_real, 4096)
        CPY4(SM_WC,  W_cat,  8192)
        CPY4(SM_BPZ, b_pz,   32)
        CPY4(SM_BR,  b_real, 64)
        CPY4(SM_BC,  b_cat,  128)
#undef CPY4
    }
    __syncthreads();

    const int b = blockIdx.x * blockDim.x + threadIdx.x;   // 0 .. B_TOTAL-1

    float* o_out = out;
    float* o_mpz = out + (size_t)B_TOTAL * 64;
    float* o_lvz = out + (size_t)B_TOTAL * 96;
    float* o_lpx = out + (size_t)B_TOTAL * 128;

    // ================= pz: mean_pz = s @ W_pz^T + b_pz; logvar = 0 =================
    {
        float s[SN];
        const float4* p = (const float4*)(samp_s + (size_t)b * SN);
#pragma unroll
        for (int i = 0; i < 8; i++) {
            float4 v = p[i]; s[4*i] = v.x; s[4*i+1] = v.y; s[4*i+2] = v.z; s[4*i+3] = v.w;
        }
        const float4 zero4 = make_float4(0.f, 0.f, 0.f, 0.f);
#pragma unroll
        for (int z4 = 0; z4 < ZN; z4 += 4) {
            float mz[4];
#pragma unroll
            for (int zz = 0; zz < 4; zz++) {
                const int z = z4 + zz;
                float a0 = 0.f, a1 = 0.f, a2 = 0.f, a3 = 0.f;
                const float4* wrow = (const float4*)(sm + SM_WPZ + z * SN);
#pragma unroll
                for (int j = 0; j < 8; j++) {
                    float4 w = wrow[j];
                    a0 = fmaf(w.x, s[4*j],   a0);
                    a1 = fmaf(w.y, s[4*j+1], a1);
                    a2 = fmaf(w.z, s[4*j+2], a2);
                    a3 = fmaf(w.w, s[4*j+3], a3);
                }
                mz[zz] = sm[SM_BPZ + z] + ((a0 + a1) + (a2 + a3));
            }
            *(float4*)(o_mpz + (size_t)b * ZN + z4) = make_float4(mz[0], mz[1], mz[2], mz[3]);
            *(float4*)(o_lvz + (size_t)b * ZN + z4) = zero4;
        }
    }

    // ================= load y (register resident) =================
    float y[D_DIM];
    {
        const float4* p = (const float4*)(y_lat + (size_t)b * D_DIM);
#pragma unroll
        for (int i = 0; i < 16; i++) {
            float4 v = p[i]; y[4*i] = v.x; y[4*i+1] = v.y; y[4*i+2] = v.z; y[4*i+3] = v.w;
        }
    }

    // ================= real features =================
#pragma unroll 1
    for (int r4 = 0; r4 < NR; r4 += 4) {
        float4 d4 = *(const float4*)(onehot + (size_t)b * 192 + r4);
        int4  ms4 = *(const int4*)(miss_mask + (size_t)b * 64 + r4);
        float darr[4] = {d4.x, d4.y, d4.z, d4.w};
        int   marr[4] = {ms4.x, ms4.y, ms4.z, ms4.w};
        float outv[4], lpv[4];
#pragma unroll
        for (int rr = 0; rr < 4; rr++) {
            const int r = r4 + rr;
            float mu = sm[SM_BR + 2*r], lv = sm[SM_BR + 2*r + 1];
            const float4* w4 = (const float4*)(sm + SM_WR + r * 128);
#pragma unroll
            for (int d2 = 0; d2 < 32; d2++) {
                float4 w = w4[d2];
                const int d = 2 * d2;
                mu = fmaf(y[d],   w.x, mu);
                lv = fmaf(y[d],   w.y, lv);
                mu = fmaf(y[d+1], w.z, mu);
                lv = fmaf(y[d+1], w.w, lv);
            }
            const float nz = normal_from_bits(tf_fold(kn0, kn1, kn2,
                                              (unsigned)b * 32u + (unsigned)r));
            float dv = darr[rr]; if (dv != dv) dv = 0.f;   // nan_to_num
            const float miss = (float)marr[rr];
            const float diff = dv - mu;
            lpv[rr]  = -0.5f * ((1.8378770664f + lv) + diff * diff * __expf(-lv)) * miss;
            outv[rr] = fmaf(__expf(0.5f * lv), nz, mu);
        }
        *(float4*)(o_out + (size_t)b * 64 + r4) = make_float4(outv[0], outv[1], outv[2], outv[3]);
        *(float4*)(o_lpx + (size_t)b * 64 + r4) = make_float4(lpv[0], lpv[1], lpv[2], lpv[3]);
    }

    // ================= categorical features =================
#pragma unroll 1
    for (int c = 0; c < NC; c++) {
        float4 bc = *(const float4*)(sm + SM_BC + 4 * c);
        float l1 = bc.x, l2 = bc.y, l3 = bc.z, l4 = bc.w;
        const float4* w4 = (const float4*)(sm + SM_WC + c * 256);
#pragma unroll
        for (int d = 0; d < 64; d++) {
            float4 w = w4[d];
            const float yd = y[d];
            l1 = fmaf(yd, w.x, l1);
            l2 = fmaf(yd, w.y, l2);
            l3 = fmaf(yd, w.z, l3);
            l4 = fmaf(yd, w.w, l4);
        }
        const unsigned base = ((unsigned)b * 32u + (unsigned)c) * 5u;
        unsigned g[5];
#pragma unroll
        for (int k = 0; k < 5; k++)
            g[k] = tf_fold(kg0, kg1, kg2, base + (unsigned)k);

        float dat5[5];
        const float* pd = onehot + (size_t)b * 192 + 32 + 5 * c;
#pragma unroll
        for (int k = 0; k < 5; k++) dat5[k] = pd[k];
        const float miss = (float)miss_mask[(size_t)b * 64 + 32 + c];

        float ov, lpv;
        cat_row(l1, l2, l3, l4, g, dat5, miss, ov, lpv);

        o_out[(size_t)b * 64 + 32 + c] = ov;
        o_lpx[(size_t)b * 64 + 32 + c] = lpv;
    }
}

extern "C" void kernel_launch(void* const* d_in, const int* in_sizes, int n_in,
                              void* d_out, int out_size) {
    const float* y_lat  = (const float*)d_in[0];
    const float* samp_s = (const float*)d_in[1];
    const float* onehot = (const float*)d_in[2];
    // d_in[3] = static_types (compile-time known layout; unused)
    const int*   mask   = (const int*)d_in[4];
    const float* W_pz   = (const float*)d_in[5];
    const float* b_pz   = (const float*)d_in[6];
    const float* W_real = (const float*)d_in[7];
    const float* b_real = (const float*)d_in[8];
    const float* W_cat  = (const float*)d_in[9];
    const float* b_cat  = (const float*)d_in[10];
    float* out = (float*)d_out;

    // jax.random.key(42) = (0, 42); partitionable (foldlike) split:
    // key_i = threefry((0,42), (0, i)), both output words form the subkey.
    unsigned kn0, kn1, kg0, kg1;
    threefry_full(0u, 42u, 0u, 0u, kn0, kn1);   // k_norm
    threefry_full(0u, 42u, 0u, 1u, kg0, kg1);   // k_gum
    const unsigned kn2 = kn0 ^ kn1 ^ 0x1BD11BDAu;
    const unsigned kg2 = kg0 ^ kg1 ^ 0x1BD11BDAu;

    cudaFuncSetAttribute(decoder_kernel,
                         cudaFuncAttributeMaxDynamicSharedMemorySize, SM_TOTAL * 4);
    decoder_kernel<<<B_TOTAL / 256, 256, SM_TOTAL * 4>>>(
        y_lat, samp_s, onehot, mask, W_pz, b_pz, W_real, b_real, W_cat, b_cat,
        out, kn0, kn1, kn2, kg0, kg1, kg2);
}

// round 7
// speedup vs baseline: 2.2091x; 1.2661x over previous
#include <cuda_runtime.h>
#include <cstdint>

#define B_TOTAL 262144
#define D_DIM   64
#define NR      32
#define NC      32
#define SN      32
#define ZN      32

typedef unsigned long long u64t;

// shared memory layout in floats
#define SM_WPZ   0          // 1024  W_pz[z][j]           (K-pairs contiguous)
#define SM_WR    1024       // 4096  W_real[r][o][d]      (transposed, K-pairs contiguous)
#define SM_WC    5120       // 8192  W_cat[c][k][d]       (transposed, K-pairs contiguous)
#define SM_BPZ   13312      // 32
#define SM_BR    13344      // 64   [r][o]
#define SM_BC    13408      // 128  [c][k]
#define SM_TILEA 13536      // 8 warps x 640 floats (32 rows x 20 stride)
#define SM_TILEB 18656      // 8 warps x 640 floats
#define SM_TOTAL 23776      // floats -> 95104 bytes

// ---------------- packed f32x2 helpers ----------------
__device__ __forceinline__ u64t ffma2(u64t a, u64t b, u64t c) {
    u64t d;
    asm("fma.rn.f32x2 %0, %1, %2, %3;" : "=l"(d) : "l"(a), "l"(b), "l"(c));
    return d;
}
__device__ __forceinline__ float pair_sum(u64t v) {
    unsigned lo, hi;
    asm("mov.b64 {%0, %1}, %2;" : "=r"(lo), "=r"(hi) : "l"(v));
    return __uint_as_float(lo) + __uint_as_float(hi);
}

// ---------------- threefry2x32 (JAX schedule) ----------------
#define TF_ROUND(r) do { x0 += x1; x1 = (x1 << (r)) | (x1 >> (32 - (r))); x1 ^= x0; } while (0)

__host__ __device__ __forceinline__ void threefry_full(unsigned k0, unsigned k1,
                                                       unsigned x0, unsigned x1,
                                                       unsigned &o0, unsigned &o1) {
    const unsigned k2 = k0 ^ k1 ^ 0x1BD11BDAu;
    x0 += k0; x1 += k1;
    TF_ROUND(13); TF_ROUND(15); TF_ROUND(26); TF_ROUND(6);
    x0 += k1; x1 += k2 + 1u;
    TF_ROUND(17); TF_ROUND(29); TF_ROUND(16); TF_ROUND(24);
    x0 += k2; x1 += k0 + 2u;
    TF_ROUND(13); TF_ROUND(15); TF_ROUND(26); TF_ROUND(6);
    x0 += k0; x1 += k1 + 3u;
    TF_ROUND(17); TF_ROUND(29); TF_ROUND(16); TF_ROUND(24);
    x0 += k1; x1 += k2 + 4u;
    TF_ROUND(13); TF_ROUND(15); TF_ROUND(26); TF_ROUND(6);
    x0 += k2; x1 += k0 + 5u;
    o0 = x0; o1 = x1;
}

// Partitionable threefry 32-bit sample: counter pair (hi=0, lo=ctr), folded o0^o1.
__device__ __forceinline__ unsigned tf_fold(unsigned k0, unsigned k1, unsigned k2,
                                            unsigned ctr) {
    unsigned x0 = k0;            // 0 + k0
    unsigned x1 = ctr + k1;
    TF_ROUND(13); TF_ROUND(15); TF_ROUND(26); TF_ROUND(6);
    x0 += k1; x1 += k2 + 1u;
    TF_ROUND(17); TF_ROUND(29); TF_ROUND(16); TF_ROUND(24);
    x0 += k2; x1 += k0 + 2u;
    TF_ROUND(13); TF_ROUND(15); TF_ROUND(26); TF_ROUND(6);
    x0 += k0; x1 += k1 + 3u;
    TF_ROUND(17); TF_ROUND(29); TF_ROUND(16); TF_ROUND(24);
    x0 += k1; x1 += k2 + 4u;
    TF_ROUND(13); TF_ROUND(15); TF_ROUND(26); TF_ROUND(6);
    x0 += k2; x1 += k0 + 5u;
    return x0 ^ x1;
}

// bits -> float in [0, 1-2^-23]
__device__ __forceinline__ float bits_to_unit(unsigned b) {
    return __uint_as_float((b >> 9) | 0x3f800000u) - 1.0f;
}

// XLA ErfInv32 (Giles polynomial), fast-log variant
__device__ __forceinline__ float erfinv_xla(float x) {
    float w = -__logf(fmaf(-x, x, 1.0f));
    float p;
    if (w < 5.0f) {
        w = w - 2.5f;
        p = 2.81022636e-08f;
        p = fmaf(p, w, 3.43273939e-07f);
        p = fmaf(p, w, -3.5233877e-06f);
        p = fmaf(p, w, -4.39150654e-06f);
        p = fmaf(p, w, 0.00021858087f);
        p = fmaf(p, w, -0.00125372503f);
        p = fmaf(p, w, -0.00417768164f);
        p = fmaf(p, w, 0.246640727f);
        p = fmaf(p, w, 1.50140941f);
    } else {
        w = sqrtf(w) - 3.0f;
        p = -0.000200214257f;
        p = fmaf(p, w, 0.000100950558f);
        p = fmaf(p, w, 0.00134934322f);
        p = fmaf(p, w, -0.00367342844f);
        p = fmaf(p, w, 0.00573950773f);
        p = fmaf(p, w, -0.0076224613f);
        p = fmaf(p, w, 0.00943887047f);
        p = fmaf(p, w, 1.00167406f);
        p = fmaf(p, w, 2.83297682f);
    }
    return p * x;
}

__device__ __forceinline__ float normal_from_bits(unsigned b) {
    float f = bits_to_unit(b);
    float u = fmaf(f, 2.0f, -0.99999994f);
    u = fmaxf(-0.99999994f, u);
    return 1.41421356f * erfinv_xla(u);
}

__device__ __forceinline__ float gumbel_from_bits(unsigned b) {
    float f = bits_to_unit(b);
    float t = -__logf(fmaxf(f, 1.17549435e-38f));
    t = fmaxf(t, 1.17549435e-38f);
    return -__logf(t);
}

__device__ __forceinline__ void cat_row(float l1, float l2, float l3, float l4,
                                        const unsigned gb[5],
                                        const float* __restrict__ data5, float miss,
                                        float &out_val, float &lp_val) {
    float m = fmaxf(0.0f, fmaxf(fmaxf(l1, l2), fmaxf(l3, l4)));
    float e0 = __expf(0.0f - m);
    float e1 = __expf(l1 - m);
    float e2 = __expf(l2 - m);
    float e3 = __expf(l3 - m);
    float e4 = __expf(l4 - m);
    float S  = ((e0 + e1) + (e2 + e3)) + e4;
    float logS = __logf(S);
    float lp =            data5[0] * ((0.0f - m) - logS);
    lp = fmaf(data5[1], (l1 - m) - logS, lp);
    lp = fmaf(data5[2], (l2 - m) - logS, lp);
    lp = fmaf(data5[3], (l3 - m) - logS, lp);
    lp = fmaf(data5[4], (l4 - m) - logS, lp);
    lp_val = lp * miss;

    float z0 = gumbel_from_bits(gb[0]);
    float z1 = l1 + gumbel_from_bits(gb[1]);
    float z2 = l2 + gumbel_from_bits(gb[2]);
    float z3 = l3 + gumbel_from_bits(gb[3]);
    float z4 = l4 + gumbel_from_bits(gb[4]);
    float best = z0; int arg = 0;
    if (z1 > best) { best = z1; arg = 1; }
    if (z2 > best) { best = z2; arg = 2; }
    if (z3 > best) { best = z3; arg = 3; }
    if (z4 > best) { best = z4; arg = 4; }
    out_val = (float)arg;
}

// Coalesced flush of one 32x16 per-warp tile chunk to gmem.
// Each STG.128 covers 8 rows x 64B-contiguous segments -> 16 sectors (optimal).
__device__ __forceinline__ void flush_tile(const float* tile, float* gbase,
                                           int stride, int c0, int lane) {
#pragma unroll
    for (int it = 0; it < 4; it++) {
        const int row = it * 8 + (lane >> 2);
        const int col = (lane & 3) * 4;
        float4 v = *(const float4*)(tile + row * 20 + col);
        *(float4*)(gbase + (size_t)row * stride + c0 + col) = v;
    }
}

__global__ __launch_bounds__(256, 2)
void decoder_kernel(const float* __restrict__ y_lat, const float* __restrict__ samp_s,
                    const float* __restrict__ onehot, const int* __restrict__ miss_mask,
                    const float* __restrict__ W_pz, const float* __restrict__ b_pz,
                    const float* __restrict__ W_real, const float* __restrict__ b_real,
                    const float* __restrict__ W_cat, const float* __restrict__ b_cat,
                    float* __restrict__ out,
                    unsigned kn0, unsigned kn1, unsigned kn2,
                    unsigned kg0, unsigned kg1, unsigned kg2) {
    extern __shared__ float sm[];
    {
        const int tid = threadIdx.x;
        const int nt = blockDim.x;
        for (int i = tid; i < 256; i += nt)
            ((float4*)(sm + SM_WPZ))[i] = ((const float4*)W_pz)[i];
        // transpose W_real [r][d][o] -> [r][o][d]
        for (int i = tid; i < 4096; i += nt) {
            int r = i >> 7, o = (i >> 6) & 1, d = i & 63;
            sm[SM_WR + i] = W_real[(r << 7) + (d << 1) + o];
        }
        // transpose W_cat [c][d][k] -> [c][k][d]
        for (int i = tid; i < 8192; i += nt) {
            int c = i >> 8, k = (i >> 6) & 3, d = i & 63;
            sm[SM_WC + i] = W_cat[(c << 8) + (d << 2) + k];
        }
        for (int i = tid; i < 8; i += nt)
            ((float4*)(sm + SM_BPZ))[i] = ((const float4*)b_pz)[i];
        for (int i = tid; i < 16; i += nt)
            ((float4*)(sm + SM_BR))[i] = ((const float4*)b_real)[i];
        for (int i = tid; i < 32; i += nt)
            ((float4*)(sm + SM_BC))[i] = ((const float4*)b_cat)[i];
    }
    __syncthreads();

    const int b = blockIdx.x * blockDim.x + threadIdx.x;   // row index
    const int lane = threadIdx.x & 31;
    const int warp = threadIdx.x >> 5;
    const int rowbase = b & ~31;

    float* tileA = sm + SM_TILEA + warp * 640;
    float* tileB = sm + SM_TILEB + warp * 640;

    float* o_out = out;
    float* o_mpz = out + (size_t)B_TOTAL * 64;
    float* o_lpx = out + (size_t)B_TOTAL * 128;
    // o_lvz (out + B*96) is zero-filled by a separate kernel.

    // ================= pz: mean_pz = s @ W_pz^T + b_pz =================
    {
        u64t s2[16];
        const ulonglong2* ps = (const ulonglong2*)(samp_s + (size_t)b * SN);
#pragma unroll
        for (int i = 0; i < 8; i++) {
            ulonglong2 v = ps[i]; s2[2*i] = v.x; s2[2*i+1] = v.y;
        }
#pragma unroll 1
        for (int z = 0; z < ZN; z++) {
            u64t acc = 0;
            const ulonglong2* w = (const ulonglong2*)(sm + SM_WPZ + z * SN);
#pragma unroll
            for (int j = 0; j < 8; j++) {   // 8 x 4 floats = 32 = SN
                ulonglong2 v = w[j];
                acc = ffma2(s2[2*j],   v.x, acc);
                acc = ffma2(s2[2*j+1], v.y, acc);
            }
            tileA[lane * 20 + (z & 15)] = sm[SM_BPZ + z] + pair_sum(acc);
            if ((z & 15) == 15) {
                __syncwarp();
                flush_tile(tileA, o_mpz + (size_t)rowbase * 32, 32, z & 16, lane);
                __syncwarp();
            }
        }
    }

    // ================= load y as K-pairs (register resident) =================
    u64t y2[32];
    {
        const ulonglong2* py = (const ulonglong2*)(y_lat + (size_t)b * D_DIM);
#pragma unroll
        for (int i = 0; i < 16; i++) {
            ulonglong2 v = py[i]; y2[2*i] = v.x; y2[2*i+1] = v.y;
        }
    }

    // ================= real features =================
#pragma unroll 1
    for (int r4 = 0; r4 < NR; r4 += 4) {
        float4 d4 = *(const float4*)(onehot + (size_t)b * 192 + r4);
        int4  ms4 = *(const int4*)(miss_mask + (size_t)b * 64 + r4);
        float darr[4] = {d4.x, d4.y, d4.z, d4.w};
        int   marr[4] = {ms4.x, ms4.y, ms4.z, ms4.w};
        float outv[4], lpv[4];
#pragma unroll
        for (int rr = 0; rr < 4; rr++) {
            const int r = r4 + rr;
            u64t am = 0, av = 0;
            const ulonglong2* wm = (const ulonglong2*)(sm + SM_WR + r * 128);
            const ulonglong2* wv = wm + 16;   // +64 floats (16 x 16B)
#pragma unroll
            for (int j = 0; j < 16; j++) {    // 16 x 4 floats = 64 = D_DIM
                ulonglong2 m2 = wm[j], v2 = wv[j];
                am = ffma2(y2[2*j],   m2.x, am);
                am = ffma2(y2[2*j+1], m2.y, am);
                av = ffma2(y2[2*j],   v2.x, av);
                av = ffma2(y2[2*j+1], v2.y, av);
            }
            const float mu = sm[SM_BR + 2*r]     + pair_sum(am);
            const float lv = sm[SM_BR + 2*r + 1] + pair_sum(av);

            const float nz = normal_from_bits(tf_fold(kn0, kn1, kn2,
                                              (unsigned)b * 32u + (unsigned)r));
            float dv = darr[rr]; if (dv != dv) dv = 0.f;   // nan_to_num
            const float miss = (float)marr[rr];
            const float diff = dv - mu;
            lpv[rr]  = -0.5f * ((1.8378770664f + lv) + diff * diff * __expf(-lv)) * miss;
            outv[rr] = fmaf(__expf(0.5f * lv), nz, mu);
        }
        *(float4*)(tileA + lane * 20 + (r4 & 12)) = make_float4(outv[0], outv[1], outv[2], outv[3]);
        *(float4*)(tileB + lane * 20 + (r4 & 12)) = make_float4(lpv[0], lpv[1], lpv[2], lpv[3]);
        if ((r4 & 12) == 12) {
            __syncwarp();
            flush_tile(tileA, o_out + (size_t)rowbase * 64, 64, r4 & 16, lane);
            flush_tile(tileB, o_lpx + (size_t)rowbase * 64, 64, r4 & 16, lane);
            __syncwarp();
        }
    }

    // ================= categorical features (groups of 4) =================
#pragma unroll 1
    for (int g = 0; g < 8; g++) {
        const float4* pd4 = (const float4*)(onehot + (size_t)b * 192 + 32 + 20 * g);
        float dat[20];
        *(float4*)(dat +  0) = pd4[0];
        *(float4*)(dat +  4) = pd4[1];
        *(float4*)(dat +  8) = pd4[2];
        *(float4*)(dat + 12) = pd4[3];
        *(float4*)(dat + 16) = pd4[4];
        int4 ms = *(const int4*)(miss_mask + (size_t)b * 64 + 32 + 4 * g);
        int marr[4] = {ms.x, ms.y, ms.z, ms.w};
#pragma unroll
        for (int cc = 0; cc < 4; cc++) {
            const int c = 4 * g + cc;
            u64t a1 = 0, a2 = 0, a3 = 0, a4 = 0;
            const ulonglong2* w1 = (const ulonglong2*)(sm + SM_WC + c * 256);
            const ulonglong2* w2 = w1 + 16;   // +64 floats
            const ulonglong2* w3 = w1 + 32;   // +128 floats
            const ulonglong2* w4 = w1 + 48;   // +192 floats
#pragma unroll
            for (int j = 0; j < 16; j++) {    // 16 x 4 floats = 64 = D_DIM
                ulonglong2 p1 = w1[j], p2 = w2[j], p3 = w3[j], p4 = w4[j];
                a1 = ffma2(y2[2*j],   p1.x, a1);
                a1 = ffma2(y2[2*j+1], p1.y, a1);
                a2 = ffma2(y2[2*j],   p2.x, a2);
                a2 = ffma2(y2[2*j+1], p2.y, a2);
                a3 = ffma2(y2[2*j],   p3.x, a3);
                a3 = ffma2(y2[2*j+1], p3.y, a3);
                a4 = ffma2(y2[2*j],   p4.x, a4);
                a4 = ffma2(y2[2*j+1], p4.y, a4);
            }
            float4 bc = *(const float4*)(sm + SM_BC + 4 * c);
            const float l1 = bc.x + pair_sum(a1);
            const float l2 = bc.y + pair_sum(a2);
            const float l3 = bc.z + pair_sum(a3);
            const float l4 = bc.w + pair_sum(a4);

            const unsigned base = ((unsigned)b * 32u + (unsigned)c) * 5u;
            unsigned gb[5];
#pragma unroll
            for (int k = 0; k < 5; k++)
                gb[k] = tf_fold(kg0, kg1, kg2, base + (unsigned)k);

            float dat5[5];
#pragma unroll
            for (int k = 0; k < 5; k++) dat5[k] = dat[5 * cc + k];

            float ov, lpval;
            cat_row(l1, l2, l3, l4, gb, dat5, (float)marr[cc], ov, lpval);

            tileA[lane * 20 + (c & 15)] = ov;
            tileB[lane * 20 + (c & 15)] = lpval;
        }
        if ((g & 3) == 3) {
            __syncwarp();
            const int c0 = 32 + ((g & 4) ? 16 : 0);
            flush_tile(tileA, o_out + (size_t)rowbase * 64, 64, c0, lane);
            flush_tile(tileB, o_lpx + (size_t)rowbase * 64, 64, c0, lane);
            __syncwarp();
        }
    }
}

__global__ __launch_bounds__(256)
void zero_lvz_kernel(float4* __restrict__ p) {
    const int i = blockIdx.x * blockDim.x + threadIdx.x;
    p[i] = make_float4(0.f, 0.f, 0.f, 0.f);
}

extern "C" void kernel_launch(void* const* d_in, const int* in_sizes, int n_in,
                              void* d_out, int out_size) {
    const float* y_lat  = (const float*)d_in[0];
    const float* samp_s = (const float*)d_in[1];
    const float* onehot = (const float*)d_in[2];
    // d_in[3] = static_types (compile-time known layout; unused)
    const int*   mask   = (const int*)d_in[4];
    const float* W_pz   = (const float*)d_in[5];
    const float* b_pz   = (const float*)d_in[6];
    const float* W_real = (const float*)d_in[7];
    const float* b_real = (const float*)d_in[8];
    const float* W_cat  = (const float*)d_in[9];
    const float* b_cat  = (const float*)d_in[10];
    float* out = (float*)d_out;

    // jax.random.key(42) = (0, 42); partitionable (foldlike) split:
    // key_i = threefry((0,42), (0, i)), both output words form the subkey.
    unsigned kn0, kn1, kg0, kg1;
    threefry_full(0u, 42u, 0u, 0u, kn0, kn1);   // k_norm
    threefry_full(0u, 42u, 0u, 1u, kg0, kg1);   // k_gum
    const unsigned kn2 = kn0 ^ kn1 ^ 0x1BD11BDAu;
    const unsigned kg2 = kg0 ^ kg1 ^ 0x1BD11BDAu;

    cudaFuncSetAttribute(decoder_kernel,
                         cudaFuncAttributeMaxDynamicSharedMemorySize, SM_TOTAL * 4);
    decoder_kernel<<<B_TOTAL / 256, 256, SM_TOTAL * 4>>>(
        y_lat, samp_s, onehot, mask, W_pz, b_pz, W_real, b_real, W_cat, b_cat,
        out, kn0, kn1, kn2, kg0, kg1, kg2);

    // log_var_pz = zeros: B*32 floats = 2,097,152 float4
    float4* lvz = (float4*)(out + (size_t)B_TOTAL * 96);
    zero_lvz_kernel<<<(B_TOTAL * 32 / 4) / 256, 256>>>(lvz);
}